// round 16
// baseline (speedup 1.0000x reference)
#include <cuda_runtime.h>
#include <cuda_fp16.h>
#include <math.h>
#include <stdint.h>

#define BB   4
#define CC   64
#define HH   192
#define WW   192
#define HWX  (HH*WW)
#define OFFC 18
#define HID  4

// warp-level f16 MMA, fp32 accumulate: D(16x8) += A(16x16) * B(16x8)
#define MMA_F16(d0,d1,d2,d3, a0,a1,a2,a3, b0,b1)                               \
    asm volatile("mma.sync.aligned.m16n8k16.row.col.f32.f16.f16.f32 "          \
        "{%0,%1,%2,%3}, {%4,%5,%6,%7}, {%8,%9}, {%0,%1,%2,%3};"                \
        : "+f"(d0), "+f"(d1), "+f"(d2), "+f"(d3)                               \
        : "r"(a0), "r"(a1), "r"(a2), "r"(a3), "r"(b0), "r"(b1))

#define LDSM_X4(r0,r1,r2,r3,a)                                                 \
    asm volatile("ldmatrix.sync.aligned.m8n8.x4.shared.b16 {%0,%1,%2,%3}, [%4];" \
        : "=r"(r0), "=r"(r1), "=r"(r2), "=r"(r3) : "r"(a))
#define LDSM_X2(r0,r1,a)                                                       \
    asm volatile("ldmatrix.sync.aligned.m8n8.x2.shared.b16 {%0,%1}, [%2];"     \
        : "=r"(r0), "=r"(r1) : "r"(a))

__device__ __forceinline__ uint32_t smaddr(const void* p) {
    return (uint32_t)__cvta_generic_to_shared(p);
}

// scratch (device globals; allocations are forbidden)
__device__ float g_off[BB*OFFC*HH*WW];            // 10.6 MB
__device__ float g_h  [BB*CC*HH*WW];              // 37.7 MB fp32 NCHW h
__device__ __align__(16) __half g_hTh[BB*HWX*CC]; // 18.9 MB NHWC fp16 h
__device__ __align__(16) __half g_xTh[BB*HWX*CC]; // 18.9 MB NHWC fp16 x
__device__ __half g_Yh[BB*49*HWX];                // 14.5 MB tap maps (fp16)
__device__ float g_pool[BB*CC];
__device__ float g_cw  [BB*CC];
__device__ __align__(16) __half g_dwTh[9*CC*CC];  // [kk][o][c] fp16
__device__ __align__(16) uint32_t g_offwH[9*24*36]; // [tap][o(24)][word36] half2

// offset-conv v3 smem (words): halo [396][36] + B [9*24][36]
#define OC_HALO_W (396*36)
#define OC_B_W    (9*24*36)
#define OC_SMEM_BYTES ((OC_HALO_W + OC_B_W)*4)    // 88128

// ---------------------------------------------------------------------------
// K0: weight prep
// ---------------------------------------------------------------------------
__global__ __launch_bounds__(256) void transpose_w_kernel(
        const float* __restrict__ dw, const float* __restrict__ off_w) {
    int d = blockIdx.x*256 + threadIdx.x;
    if (blockIdx.x == 0) g_pool[threadIdx.x] = 0.f;
    if (d < 9*CC*CC) {
        int kk = d >> 12;
        int o  = (d >> 6) & 63;
        int c  = d & 63;
        g_dwTh[d] = __float2half_rn(dw[(o*CC + c)*9 + kk]);
    } else {
        int e = d - 9*CC*CC;
        if (e < 9*24*36) {
            int tap = e / (24*36);
            int rem = e % (24*36);
            int o   = rem / 36;
            int w   = rem % 36;
            __half2 v = __half2half2(__float2half(0.f));
            if (o < OFFC && w < 32)
                v = __floats2half2_rn(off_w[(o*CC + 2*w    )*9 + tap],
                                      off_w[(o*CC + 2*w + 1)*9 + tap]);
            g_offwH[e] = *(const uint32_t*)&v;
        }
    }
}

// ---------------------------------------------------------------------------
// K0b: NCHW fp32 -> NHWC fp16 transpose of x
// ---------------------------------------------------------------------------
__global__ __launch_bounds__(256) void nhwc_kernel(const float* __restrict__ x) {
    __shared__ float ts[64*33];
    const int tid = threadIdx.x;
    const int blk = blockIdx.x;
    const int b   = blk / (HWX/32);
    const int pt  = (blk % (HWX/32)) * 32;
    const int px5 = tid & 31, cg = tid >> 5;

    #pragma unroll
    for (int it = 0; it < 8; ++it) {
        int ch = it*8 + cg;
        ts[ch*33 + px5] = x[((size_t)(b*CC + ch))*HWX + pt + px5];
    }
    __syncthreads();
    const int px = tid >> 3;
    const int g  = tid & 7;
    uint4 o;
    uint32_t* ow = (uint32_t*)&o;
    #pragma unroll
    for (int p2 = 0; p2 < 4; ++p2) {
        __half2 h = __floats2half2_rn(ts[(g*8 + 2*p2)*33 + px],
                                      ts[(g*8 + 2*p2 + 1)*33 + px]);
        ow[p2] = *(uint32_t*)&h;
    }
    ((uint4*)g_xTh)[((size_t)b*HWX + pt + px)*8 + g] = o;
}

// ---------------------------------------------------------------------------
// K1 v3: 3x3 conv 64 -> 18 via f16 MMA from NHWC fp16 halo (R14, validated)
// ---------------------------------------------------------------------------
__global__ __launch_bounds__(256) void offset_conv_kernel(
        const float* __restrict__ off_b) {
    extern __shared__ uint32_t osm[];
    uint32_t* halo = osm;               // [pos 0..395][36 words]
    uint32_t* Bs   = osm + OC_HALO_W;   // [tap*24+o][36 words]

    const int tid = threadIdx.x;
    const int wid = tid >> 5, lid = tid & 31;
    const int bx = blockIdx.x, by = blockIdx.y, b = blockIdx.z;
    const int r4 = lid >> 2, klo = lid & 3;

    {
        const uint4* xs = (const uint4*)g_xTh + (size_t)b*HWX*8;
        for (int t = tid; t < 396*8; t += 256) {
            int pos = t >> 3, c8 = t & 7;
            int rr = pos / 66, q = pos % 66;
            int gy = by*4 + rr - 1, gx = bx*64 + q - 1;
            uint4 v = make_uint4(0u, 0u, 0u, 0u);
            if ((unsigned)gy < (unsigned)HH && (unsigned)gx < (unsigned)WW)
                v = xs[((size_t)gy*WW + gx)*8 + c8];
            *(uint4*)(halo + pos*36 + c8*4) = v;
        }
    }
    for (int t = tid; t < 9*24*9; t += 256)
        ((uint4*)Bs)[t] = ((const uint4*)g_offwH)[t];
    __syncthreads();

    float d[2][3][4];
    #pragma unroll
    for (int mt2 = 0; mt2 < 2; ++mt2)
        #pragma unroll
        for (int nt = 0; nt < 3; ++nt)
            { d[mt2][nt][0]=0.f; d[mt2][nt][1]=0.f; d[mt2][nt][2]=0.f; d[mt2][nt][3]=0.f; }

    const int mtA = wid*2;
    #pragma unroll
    for (int tap = 0; tap < 9; ++tap) {
        const int i = tap/3, j = tap%3;
        #pragma unroll
        for (int s = 0; s < 4; ++s) {
            const int kw = s*8 + klo;
            uint32_t a[2][4];
            #pragma unroll
            for (int mt2 = 0; mt2 < 2; ++mt2) {
                int m = (mtA + mt2)*16 + r4;
                int pos = ((m >> 6) + i)*66 + (m & 63) + j;
                a[mt2][0] = halo[ pos     *36 + kw    ];
                a[mt2][1] = halo[(pos + 8)*36 + kw    ];
                a[mt2][2] = halo[ pos     *36 + kw + 4];
                a[mt2][3] = halo[(pos + 8)*36 + kw + 4];
            }
            #pragma unroll
            for (int nt = 0; nt < 3; ++nt) {
                uint32_t b0 = Bs[(tap*24 + nt*8 + r4)*36 + kw];
                uint32_t b1 = Bs[(tap*24 + nt*8 + r4)*36 + kw + 4];
                MMA_F16(d[0][nt][0], d[0][nt][1], d[0][nt][2], d[0][nt][3],
                        a[0][0], a[0][1], a[0][2], a[0][3], b0, b1);
                MMA_F16(d[1][nt][0], d[1][nt][1], d[1][nt][2], d[1][nt][3],
                        a[1][0], a[1][1], a[1][2], a[1][3], b0, b1);
            }
        }
    }

    #pragma unroll
    for (int mt2 = 0; mt2 < 2; ++mt2) {
        int m0 = (mtA + mt2)*16 + r4;
        int y0 = by*4 + (m0 >> 6), x0 = bx*64 + (m0 & 63);
        #pragma unroll
        for (int nt = 0; nt < 3; ++nt) {
            int o0 = nt*8 + 2*klo, o1 = o0 + 1;
            if (o0 < OFFC) {
                float bv = off_b[o0];
                float* dst = &g_off[((size_t)(b*OFFC + o0)*HH + y0)*WW + x0];
                dst[0] = d[mt2][nt][0] + bv;
                dst[8] = d[mt2][nt][2] + bv;
            }
            if (o1 < OFFC) {
                float bv = off_b[o1];
                float* dst = &g_off[((size_t)(b*OFFC + o1)*HH + y0)*WW + x0];
                dst[0] = d[mt2][nt][1] + bv;
                dst[8] = d[mt2][nt][3] + bv;
            }
        }
    }
}

// ---------------------------------------------------------------------------
// K2: deformable conv, f16 mma + ldmatrix + cp.async; half2 lerp; 4 CTAs/SM
// ---------------------------------------------------------------------------
__global__ __launch_bounds__(256, 4) void deform_bn_kernel(
        const float* __restrict__ db,
        const float* __restrict__ gma,
        const float* __restrict__ bta,
        const float* __restrict__ mean,
        const float* __restrict__ var) {
    __shared__ uint32_t A_s[2][64*36];
    __shared__ uint32_t B_s[2][64*36];
    __shared__ float    M_s[2][512];
    __shared__ float    sc_s[64], sh_s[64];

    const int tid = threadIdx.x;
    const int wid = tid >> 5, lid = tid & 31;
    const int b   = blockIdx.z;
    const int y   = blockIdx.y;
    const int x0b = blockIdx.x * 64;

    if (tid < 64) {
        float sc = gma[tid] * rsqrtf(var[tid] + 1e-5f);
        sc_s[tid] = sc;
        sh_s[tid] = (db[tid] - mean[tid])*sc + bta[tid];
    }

    const __half* xh = g_xTh + (size_t)b*HWX*CC;

    auto compute_meta = [&](int kk, int mb) {
        if (tid < 64) {
            int xx = x0b + tid;
            int i = kk/3, j = kk%3;
            float oy = g_off[((size_t)(b*OFFC + 2*kk  )*HH + y)*WW + xx];
            float ox = g_off[((size_t)(b*OFFC + 2*kk+1)*HH + y)*WW + xx];
            float py = (float)(y  + i - 1) + oy;
            float px = (float)(xx + j - 1) + ox;
            float fy = floorf(py), fx = floorf(px);
            int yq = (int)fy, xq = (int)fx;
            float wy = py - fy, wx = px - fx;
            float vy0 = ((unsigned)yq     < (unsigned)HH) ? 1.f : 0.f;
            float vy1 = ((unsigned)(yq+1) < (unsigned)HH) ? 1.f : 0.f;
            float vx0 = ((unsigned)xq     < (unsigned)WW) ? 1.f : 0.f;
            float vx1 = ((unsigned)(xq+1) < (unsigned)WW) ? 1.f : 0.f;
            float uA = (1.f - wy)*vy0, uB = wy*vy1;
            float wA = (1.f - wx)*vx0, wB = wx*vx1;
            int yb0 = min(max(yq,   0), HH-1);
            int yb1 = min(max(yq+1, 0), HH-1);
            int xc0 = min(max(xq,   0), WW-1);
            int xc1 = min(max(xq+1, 0), WW-1);
            float* mp = M_s[mb] + tid*8;
            mp[0] = __uint_as_float((uint32_t)((yb0*WW + xc0)*CC));
            mp[1] = __uint_as_float((uint32_t)((yb1*WW + xc0)*CC));
            mp[2] = __uint_as_float((uint32_t)((xc1 - xc0)*CC));
            mp[3] = uA; mp[4] = uB; mp[5] = wA; mp[6] = wB; mp[7] = 0.f;
        }
    };
    auto stage_B = [&](int kk, int bf) {
        const uint4* src = (const uint4*)(g_dwTh + kk*4096);
        #pragma unroll 2
        for (int t = tid; t < 512; t += 256) {
            int o = t >> 3, w4 = t & 7;
            uint32_t dst = smaddr(&B_s[bf][o*36 + w4*4]);
            asm volatile("cp.async.ca.shared.global [%0], [%1], 16;"
                         :: "r"(dst), "l"(&src[o*8 + w4]) : "memory");
        }
        asm volatile("cp.async.commit_group;" ::: "memory");
    };
    auto gather = [&](int abuf, int mb) {
        const int c8 = lid & 7, pq = lid >> 3;
        #pragma unroll
        for (int it = 0; it < 2; ++it) {
            int px = (wid << 3) + (it << 2) + pq;
            const float* mp = M_s[mb] + px*8;
            float4 m0 = *(const float4*)mp;
            float4 m1 = *(const float4*)(mp + 4);
            uint32_t base0 = __float_as_uint(m0.x);
            uint32_t base1 = __float_as_uint(m0.y);
            uint32_t dx    = __float_as_uint(m0.z);
            __half2 uA2 = __float2half2_rn(m0.w);
            __half2 uB2 = __float2half2_rn(m1.x);
            __half2 wA2 = __float2half2_rn(m1.y);
            __half2 wB2 = __float2half2_rn(m1.z);
            uint4 cA0 = ((const uint4*)(xh + base0     ))[c8];
            uint4 cA1 = ((const uint4*)(xh + base0 + dx))[c8];
            uint4 cB0 = ((const uint4*)(xh + base1     ))[c8];
            uint4 cB1 = ((const uint4*)(xh + base1 + dx))[c8];
            const uint32_t* wa0 = (const uint32_t*)&cA0;
            const uint32_t* wa1 = (const uint32_t*)&cA1;
            const uint32_t* wb0 = (const uint32_t*)&cB0;
            const uint32_t* wb1 = (const uint32_t*)&cB1;
            uint4 out;
            uint32_t* ow = (uint32_t*)&out;
            #pragma unroll
            for (int p = 0; p < 4; ++p) {
                __half2 a0 = *(const __half2*)&wa0[p];
                __half2 a1 = *(const __half2*)&wa1[p];
                __half2 b0 = *(const __half2*)&wb0[p];
                __half2 b1 = *(const __half2*)&wb1[p];
                __half2 t0 = __hfma2(uA2, a0, __hmul2(uB2, b0));
                __half2 t1 = __hfma2(uA2, a1, __hmul2(uB2, b1));
                __half2 r  = __hfma2(wA2, t0, __hmul2(wB2, t1));
                ow[p] = *(const uint32_t*)&r;
            }
            ((uint4*)(&A_s[abuf][px*36]))[c8] = out;
        }
    };

    float d[2][2][4];
    #pragma unroll
    for (int mt = 0; mt < 2; ++mt)
        #pragma unroll
        for (int nt = 0; nt < 2; ++nt)
            { d[mt][nt][0]=0.f; d[mt][nt][1]=0.f; d[mt][nt][2]=0.f; d[mt][nt][3]=0.f; }

    const int mg = wid & 1, ng = wid >> 1;
    const int l8 = lid & 7, quad = lid >> 3;

    compute_meta(0, 0);
    __syncthreads();
    stage_B(0, 0);
    gather(0, 0);
    compute_meta(1, 1);
    asm volatile("cp.async.wait_group 0;" ::: "memory");
    __syncthreads();

    #pragma unroll 1
    for (int kk = 0; kk < 9; ++kk) {
        const int buf = kk & 1, nxt = buf ^ 1;
        if (kk < 8) {
            stage_B(kk + 1, nxt);
            if (kk < 7) compute_meta(kk + 2, buf);
            gather(nxt, nxt);
        }
        {
            const uint32_t* Ab = A_s[buf];
            const uint32_t* Bb = B_s[buf];
            const int arow_add = (quad & 1) ? 8 : 0;
            const int acol_add = (quad & 2) ? 4 : 0;
            const int bcol_add = (lid & 8) ? 4 : 0;
            #pragma unroll
            for (int s = 0; s < 4; ++s) {
                uint32_t a[2][4];
                #pragma unroll
                for (int mt = 0; mt < 2; ++mt) {
                    const int row = (mg*2 + mt)*16 + l8 + arow_add;
                    uint32_t addr = smaddr(&Ab[row*36 + s*8 + acol_add]);
                    LDSM_X4(a[mt][0], a[mt][1], a[mt][2], a[mt][3], addr);
                }
                #pragma unroll
                for (int nt = 0; nt < 2; ++nt) {
                    const int brow = (ng*2 + nt)*8 + l8;
                    uint32_t baddr = smaddr(&Bb[brow*36 + s*8 + bcol_add]);
                    uint32_t b0, b1;
                    LDSM_X2(b0, b1, baddr);
                    MMA_F16(d[0][nt][0], d[0][nt][1], d[0][nt][2], d[0][nt][3],
                            a[0][0], a[0][1], a[0][2], a[0][3], b0, b1);
                    MMA_F16(d[1][nt][0], d[1][nt][1], d[1][nt][2], d[1][nt][3],
                            a[1][0], a[1][1], a[1][2], a[1][3], b0, b1);
                }
            }
        }
        if (kk < 8) asm volatile("cp.async.wait_group 0;" ::: "memory");
        __syncthreads();
    }

    // epilogue: BN -> g_h (fp32 NCHW) + g_hTh (fp16 NHWC) + fused pool
    const int r4 = lid >> 2, klo = lid & 3;
    __half* hTh = g_hTh + ((size_t)b*HWX + (size_t)y*WW + x0b)*CC;
    #pragma unroll
    for (int nt = 0; nt < 2; ++nt) {
        const int o0 = (ng*2 + nt)*8 + klo*2;
        const int o1 = o0 + 1;
        const float sc0 = sc_s[o0], sh0 = sh_s[o0];
        const float sc1 = sc_s[o1], sh1 = sh_s[o1];
        float s0 = 0.f, s1 = 0.f;
        #pragma unroll
        for (int mt = 0; mt < 2; ++mt) {
            const int p0 = (mg*2 + mt)*16 + r4, p1 = p0 + 8;
            float v00 = d[mt][nt][0]*sc0 + sh0;
            float v01 = d[mt][nt][1]*sc1 + sh1;
            float v10 = d[mt][nt][2]*sc0 + sh0;
            float v11 = d[mt][nt][3]*sc1 + sh1;
            g_h[((size_t)(b*CC + o0)*HH + y)*WW + x0b + p0] = v00;
            g_h[((size_t)(b*CC + o1)*HH + y)*WW + x0b + p0] = v01;
            g_h[((size_t)(b*CC + o0)*HH + y)*WW + x0b + p1] = v10;
            g_h[((size_t)(b*CC + o1)*HH + y)*WW + x0b + p1] = v11;
            *(__half2*)&hTh[(size_t)p0*CC + o0] = __floats2half2_rn(v00, v01);
            *(__half2*)&hTh[(size_t)p1*CC + o0] = __floats2half2_rn(v10, v11);
            s0 += v00 + v10;
            s1 += v01 + v11;
        }
        #pragma unroll
        for (int off = 4; off < 32; off <<= 1) {
            s0 += __shfl_xor_sync(0xffffffffu, s0, off);
            s1 += __shfl_xor_sync(0xffffffffu, s1, off);
        }
        if (r4 == 0) {
            atomicAdd(&g_pool[b*CC + o0], s0);
            atomicAdd(&g_pool[b*CC + o1], s1);
        }
    }
}

// ---------------------------------------------------------------------------
// K3: SE MLP (hid=4)
// ---------------------------------------------------------------------------
__global__ __launch_bounds__(256) void ca_kernel(
        const float* __restrict__ w1, const float* __restrict__ b1,
        const float* __restrict__ w2, const float* __restrict__ b2) {
    __shared__ float t[BB*HID];
    const int tid = threadIdx.x;
    const int b = tid >> 6, c = tid & 63;
    if (c < HID) {
        float s = b1[c];
        for (int cc = 0; cc < CC; ++cc)
            s += w1[c*CC + cc] * (g_pool[b*CC + cc] * (1.f/(float)HWX));
        t[b*HID + c] = fmaxf(s, 0.f);
    }
    __syncthreads();
    float s = b2[c];
    #pragma unroll
    for (int h = 0; h < HID; ++h) s += w2[c*HID + h] * t[b*HID + h];
    g_cw[tid] = 1.f / (1.f + expf(-s));
}

// ---------------------------------------------------------------------------
// K4: Y GEMM: Y[p, tap] = sum_c (sa_w[c,tap]*cw[c]) * h[c,p]
// A staged directly from g_hTh (NHWC fp16)
// ---------------------------------------------------------------------------
__global__ __launch_bounds__(256) void y_gemm_kernel(
        const float* __restrict__ sa_w) {
    __shared__ uint32_t A_s[64*36];
    __shared__ uint32_t B_s[56*36];

    const int tid = threadIdx.x;
    const int wid = tid >> 5, lid = tid & 31;
    const int b   = blockIdx.y;
    const int p0b = blockIdx.x * 64;

    for (int e = tid; e < 56*32; e += 256) {
        int tap = e >> 5, c2 = e & 31;
        __half2 v = __half2half2(__float2half(0.f));
        if (tap < 49) {
            float w0 = sa_w[(2*c2  )*49 + tap] * g_cw[b*CC + 2*c2];
            float w1 = sa_w[(2*c2+1)*49 + tap] * g_cw[b*CC + 2*c2 + 1];
            v = __floats2half2_rn(w0, w1);
        }
        B_s[tap*36 + c2] = *(const uint32_t*)&v;
    }

    {
        const uint4* hs = (const uint4*)g_hTh + ((size_t)b*HWX + p0b)*8;
        #pragma unroll 2
        for (int t = tid; t < 512; t += 256) {
            int px = t >> 3, c8 = t & 7;
            *(uint4*)(&A_s[px*36 + c8*4]) = hs[px*8 + c8];
        }
    }
    __syncthreads();

    const int mt = wid & 3, ng = wid >> 2;
    const int r4 = lid >> 2, klo = lid & 3;
    const int nt0 = ng*4, ntn = ng ? 3 : 4;

    float d0[4], d1[4], d2[4], d3[4];
    #pragma unroll
    for (int i = 0; i < 4; ++i) { d0[i]=0.f; d1[i]=0.f; d2[i]=0.f; d3[i]=0.f; }

    #pragma unroll
    for (int s = 0; s < 4; ++s) {
        const int kw = s*8 + klo;
        const int row = mt*16 + r4;
        uint32_t a0 = A_s[ row     *36 + kw    ];
        uint32_t a1 = A_s[(row + 8)*36 + kw    ];
        uint32_t a2 = A_s[ row     *36 + kw + 4];
        uint32_t a3 = A_s[(row + 8)*36 + kw + 4];
        #pragma unroll
        for (int ni = 0; ni < 4; ++ni) {
            if (ni < ntn) {
                const int orow = (nt0 + ni)*8 + r4;
                uint32_t b0 = B_s[orow*36 + kw];
                uint32_t b1 = B_s[orow*36 + kw + 4];
                MMA_F16(d0[ni], d1[ni], d2[ni], d3[ni], a0, a1, a2, a3, b0, b1);
            }
        }
    }

    const int pA = p0b + mt*16 + r4;
    const int pB = pA + 8;
    #pragma unroll
    for (int ni = 0; ni < 4; ++ni) {
        if (ni < ntn) {
            int t0 = (nt0 + ni)*8 + klo*2;
            int t1 = t0 + 1;
            if (t0 < 49) {
                g_Yh[((size_t)(b*49 + t0))*HWX + pA] = __float2half(d0[ni]);
                g_Yh[((size_t)(b*49 + t0))*HWX + pB] = __float2half(d2[ni]);
            }
            if (t1 < 49) {
                g_Yh[((size_t)(b*49 + t1))*HWX + pA] = __float2half(d1[ni]);
                g_Yh[((size_t)(b*49 + t1))*HWX + pB] = __float2half(d3[ni]);
            }
        }
    }
}

// ---------------------------------------------------------------------------
// K5: final: sw = sigmoid(sum_tap Y[p+Delta,tap] + b); out = h*cw*sw
// ---------------------------------------------------------------------------
__global__ __launch_bounds__(256) void final_kernel(
        const float* __restrict__ sa_b, float* __restrict__ out) {
    __shared__ float cws[CC];
    const int idx = blockIdx.x*256 + threadIdx.x;
    const int b = idx / HWX;
    const int p = idx % HWX;
    const int y = p / WW, x = p % WW;

    if (threadIdx.x < CC) cws[threadIdx.x] = g_cw[b*CC + threadIdx.x];
    __syncthreads();

    float acc = sa_b[0];
    const __half* Yb = g_Yh + (size_t)b*49*HWX;
    #pragma unroll
    for (int dy = 0; dy < 7; ++dy) {
        int yy = y + dy - 3;
        if ((unsigned)yy >= (unsigned)HH) continue;
        #pragma unroll
        for (int dx = 0; dx < 7; ++dx) {
            int xx = x + dx - 3;
            if ((unsigned)xx >= (unsigned)WW) continue;
            acc += __half2float(Yb[(size_t)(dy*7 + dx)*HWX + yy*WW + xx]);
        }
    }
    float sw = 1.f / (1.f + expf(-acc));

    const float* hb = g_h + (size_t)b*CC*HWX + p;
    float* ob = out + (size_t)b*CC*HWX + p;
    #pragma unroll 8
    for (int c = 0; c < CC; ++c)
        ob[(size_t)c*HWX] = hb[(size_t)c*HWX] * cws[c] * sw;
}

// ---------------------------------------------------------------------------
extern "C" void kernel_launch(void* const* d_in, const int* in_sizes, int n_in,
                              void* d_out, int out_size) {
    const float* x      = (const float*)d_in[0];
    const float* off_w  = (const float*)d_in[1];
    const float* off_b  = (const float*)d_in[2];
    const float* dw     = (const float*)d_in[3];
    const float* db     = (const float*)d_in[4];
    const float* bn_g   = (const float*)d_in[5];
    const float* bn_b   = (const float*)d_in[6];
    const float* bn_m   = (const float*)d_in[7];
    const float* bn_v   = (const float*)d_in[8];
    const float* ca_w1  = (const float*)d_in[9];
    const float* ca_b1  = (const float*)d_in[10];
    const float* ca_w2  = (const float*)d_in[11];
    const float* ca_b2  = (const float*)d_in[12];
    const float* sa_w   = (const float*)d_in[13];
    const float* sa_b   = (const float*)d_in[14];
    float* out = (float*)d_out;

    cudaFuncSetAttribute(offset_conv_kernel,
                         cudaFuncAttributeMaxDynamicSharedMemorySize,
                         OC_SMEM_BYTES);

    transpose_w_kernel<<<(9*CC*CC + 9*24*36 + 255)/256, 256>>>(dw, off_w);
    nhwc_kernel       <<<BB*HWX/32, 256>>>(x);
    offset_conv_kernel<<<dim3(WW/64, HH/4, BB), 256, OC_SMEM_BYTES>>>(off_b);
    deform_bn_kernel  <<<dim3(WW/64, HH, BB), 256>>>(db, bn_g, bn_b, bn_m, bn_v);
    ca_kernel         <<<1, 256>>>(ca_w1, ca_b1, ca_w2, ca_b2);
    y_gemm_kernel     <<<dim3(HWX/64, BB), 256>>>(sa_w);
    final_kernel      <<<BB*HWX/256, 256>>>(sa_b, out);
}

// round 17
// speedup vs baseline: 1.0314x; 1.0314x over previous
#include <cuda_runtime.h>
#include <cuda_fp16.h>
#include <math.h>
#include <stdint.h>

#define BB   4
#define CC   64
#define HH   192
#define WW   192
#define HWX  (HH*WW)
#define OFFC 18
#define HID  4

// warp-level f16 MMA, fp32 accumulate: D(16x8) += A(16x16) * B(16x8)
#define MMA_F16(d0,d1,d2,d3, a0,a1,a2,a3, b0,b1)                               \
    asm volatile("mma.sync.aligned.m16n8k16.row.col.f32.f16.f16.f32 "          \
        "{%0,%1,%2,%3}, {%4,%5,%6,%7}, {%8,%9}, {%0,%1,%2,%3};"                \
        : "+f"(d0), "+f"(d1), "+f"(d2), "+f"(d3)                               \
        : "r"(a0), "r"(a1), "r"(a2), "r"(a3), "r"(b0), "r"(b1))

#define LDSM_X4(r0,r1,r2,r3,a)                                                 \
    asm volatile("ldmatrix.sync.aligned.m8n8.x4.shared.b16 {%0,%1,%2,%3}, [%4];" \
        : "=r"(r0), "=r"(r1), "=r"(r2), "=r"(r3) : "r"(a))
#define LDSM_X2(r0,r1,a)                                                       \
    asm volatile("ldmatrix.sync.aligned.m8n8.x2.shared.b16 {%0,%1}, [%2];"     \
        : "=r"(r0), "=r"(r1) : "r"(a))

__device__ __forceinline__ uint32_t smaddr(const void* p) {
    return (uint32_t)__cvta_generic_to_shared(p);
}

// scratch (device globals; allocations are forbidden)
__device__ float g_off[BB*OFFC*HH*WW];            // 10.6 MB
__device__ float g_h  [BB*CC*HH*WW];              // 37.7 MB fp32 NCHW h
__device__ __align__(16) __half g_xTh[BB*HWX*CC]; // 18.9 MB NHWC fp16 x
__device__ __half g_Yh[BB*49*HWX];                // 14.5 MB tap maps (fp16)
__device__ float g_pool[BB*CC];
__device__ float g_cw  [BB*CC];
__device__ __align__(16) __half g_dwTh[9*CC*CC];  // [kk][o][c] fp16
__device__ __align__(16) uint32_t g_offwH[9*24*36]; // [tap][o(24)][word36] half2

// offset-conv smem (words): halo [396][36] + B [9*24][36]
#define OC_HALO_W (396*36)
#define OC_B_W    (9*24*36)
#define OC_SMEM_BYTES ((OC_HALO_W + OC_B_W)*4)    // 88128

#define NHWC_BLOCKS (BB*HWX/32)                    // 4608

// ---------------------------------------------------------------------------
// K0 (merged): NCHW fp32 -> NHWC fp16 transpose of x  +  weight prep
// ---------------------------------------------------------------------------
__global__ __launch_bounds__(256) void prep_kernel(
        const float* __restrict__ x,
        const float* __restrict__ dw, const float* __restrict__ off_w) {
    const int blk = blockIdx.x;
    const int tid = threadIdx.x;
    if (blk >= NHWC_BLOCKS) {
        // weight prep blocks
        if (blk == NHWC_BLOCKS) g_pool[tid] = 0.f;
        int d = (blk - NHWC_BLOCKS)*256 + tid;
        if (d < 9*CC*CC) {
            int kk = d >> 12;
            int o  = (d >> 6) & 63;
            int c  = d & 63;
            g_dwTh[d] = __float2half_rn(dw[(o*CC + c)*9 + kk]);
        } else {
            int e = d - 9*CC*CC;
            if (e < 9*24*36) {
                int tap = e / (24*36);
                int rem = e % (24*36);
                int o   = rem / 36;
                int w   = rem % 36;
                __half2 v = __half2half2(__float2half(0.f));
                if (o < OFFC && w < 32)
                    v = __floats2half2_rn(off_w[(o*CC + 2*w    )*9 + tap],
                                          off_w[(o*CC + 2*w + 1)*9 + tap]);
                g_offwH[e] = *(const uint32_t*)&v;
            }
        }
        return;
    }
    __shared__ float ts[64*33];
    const int b   = blk / (HWX/32);
    const int pt  = (blk % (HWX/32)) * 32;
    const int px5 = tid & 31, cg = tid >> 5;

    #pragma unroll
    for (int it = 0; it < 8; ++it) {
        int ch = it*8 + cg;
        ts[ch*33 + px5] = x[((size_t)(b*CC + ch))*HWX + pt + px5];
    }
    __syncthreads();
    const int px = tid >> 3;
    const int g  = tid & 7;
    uint4 o;
    uint32_t* ow = (uint32_t*)&o;
    #pragma unroll
    for (int p2 = 0; p2 < 4; ++p2) {
        __half2 h = __floats2half2_rn(ts[(g*8 + 2*p2)*33 + px],
                                      ts[(g*8 + 2*p2 + 1)*33 + px]);
        ow[p2] = *(uint32_t*)&h;
    }
    ((uint4*)g_xTh)[((size_t)b*HWX + pt + px)*8 + g] = o;
}

// ---------------------------------------------------------------------------
// K1: 3x3 conv 64 -> 18 via f16 MMA from NHWC fp16 halo (R14, validated)
// ---------------------------------------------------------------------------
__global__ __launch_bounds__(256) void offset_conv_kernel(
        const float* __restrict__ off_b) {
    extern __shared__ uint32_t osm[];
    uint32_t* halo = osm;               // [pos 0..395][36 words]
    uint32_t* Bs   = osm + OC_HALO_W;   // [tap*24+o][36 words]

    const int tid = threadIdx.x;
    const int wid = tid >> 5, lid = tid & 31;
    const int bx = blockIdx.x, by = blockIdx.y, b = blockIdx.z;
    const int r4 = lid >> 2, klo = lid & 3;

    {
        const uint4* xs = (const uint4*)g_xTh + (size_t)b*HWX*8;
        for (int t = tid; t < 396*8; t += 256) {
            int pos = t >> 3, c8 = t & 7;
            int rr = pos / 66, q = pos % 66;
            int gy = by*4 + rr - 1, gx = bx*64 + q - 1;
            uint4 v = make_uint4(0u, 0u, 0u, 0u);
            if ((unsigned)gy < (unsigned)HH && (unsigned)gx < (unsigned)WW)
                v = xs[((size_t)gy*WW + gx)*8 + c8];
            *(uint4*)(halo + pos*36 + c8*4) = v;
        }
    }
    for (int t = tid; t < 9*24*9; t += 256)
        ((uint4*)Bs)[t] = ((const uint4*)g_offwH)[t];
    __syncthreads();

    float d[2][3][4];
    #pragma unroll
    for (int mt2 = 0; mt2 < 2; ++mt2)
        #pragma unroll
        for (int nt = 0; nt < 3; ++nt)
            { d[mt2][nt][0]=0.f; d[mt2][nt][1]=0.f; d[mt2][nt][2]=0.f; d[mt2][nt][3]=0.f; }

    const int mtA = wid*2;
    #pragma unroll
    for (int tap = 0; tap < 9; ++tap) {
        const int i = tap/3, j = tap%3;
        #pragma unroll
        for (int s = 0; s < 4; ++s) {
            const int kw = s*8 + klo;
            uint32_t a[2][4];
            #pragma unroll
            for (int mt2 = 0; mt2 < 2; ++mt2) {
                int m = (mtA + mt2)*16 + r4;
                int pos = ((m >> 6) + i)*66 + (m & 63) + j;
                a[mt2][0] = halo[ pos     *36 + kw    ];
                a[mt2][1] = halo[(pos + 8)*36 + kw    ];
                a[mt2][2] = halo[ pos     *36 + kw + 4];
                a[mt2][3] = halo[(pos + 8)*36 + kw + 4];
            }
            #pragma unroll
            for (int nt = 0; nt < 3; ++nt) {
                uint32_t b0 = Bs[(tap*24 + nt*8 + r4)*36 + kw];
                uint32_t b1 = Bs[(tap*24 + nt*8 + r4)*36 + kw + 4];
                MMA_F16(d[0][nt][0], d[0][nt][1], d[0][nt][2], d[0][nt][3],
                        a[0][0], a[0][1], a[0][2], a[0][3], b0, b1);
                MMA_F16(d[1][nt][0], d[1][nt][1], d[1][nt][2], d[1][nt][3],
                        a[1][0], a[1][1], a[1][2], a[1][3], b0, b1);
            }
        }
    }

    #pragma unroll
    for (int mt2 = 0; mt2 < 2; ++mt2) {
        int m0 = (mtA + mt2)*16 + r4;
        int y0 = by*4 + (m0 >> 6), x0 = bx*64 + (m0 & 63);
        #pragma unroll
        for (int nt = 0; nt < 3; ++nt) {
            int o0 = nt*8 + 2*klo, o1 = o0 + 1;
            if (o0 < OFFC) {
                float bv = off_b[o0];
                float* dst = &g_off[((size_t)(b*OFFC + o0)*HH + y0)*WW + x0];
                dst[0] = d[mt2][nt][0] + bv;
                dst[8] = d[mt2][nt][2] + bv;
            }
            if (o1 < OFFC) {
                float bv = off_b[o1];
                float* dst = &g_off[((size_t)(b*OFFC + o1)*HH + y0)*WW + x0];
                dst[0] = d[mt2][nt][1] + bv;
                dst[8] = d[mt2][nt][3] + bv;
            }
        }
    }
}

// ---------------------------------------------------------------------------
// K2: deformable conv: f16 mma + ldmatrix + cp.async; half2 lerp; 4 CTAs/SM
// ---------------------------------------------------------------------------
__global__ __launch_bounds__(256, 4) void deform_bn_kernel(
        const float* __restrict__ db,
        const float* __restrict__ gma,
        const float* __restrict__ bta,
        const float* __restrict__ mean,
        const float* __restrict__ var) {
    __shared__ uint32_t A_s[2][64*36];
    __shared__ uint32_t B_s[2][64*36];
    __shared__ float    M_s[2][512];
    __shared__ float    sc_s[64], sh_s[64];

    const int tid = threadIdx.x;
    const int wid = tid >> 5, lid = tid & 31;
    const int b   = blockIdx.z;
    const int y   = blockIdx.y;
    const int x0b = blockIdx.x * 64;

    if (tid < 64) {
        float sc = gma[tid] * rsqrtf(var[tid] + 1e-5f);
        sc_s[tid] = sc;
        sh_s[tid] = (db[tid] - mean[tid])*sc + bta[tid];
    }

    const __half* xh = g_xTh + (size_t)b*HWX*CC;

    auto compute_meta = [&](int kk, int mb) {
        if (tid < 64) {
            int xx = x0b + tid;
            int i = kk/3, j = kk%3;
            float oy = g_off[((size_t)(b*OFFC + 2*kk  )*HH + y)*WW + xx];
            float ox = g_off[((size_t)(b*OFFC + 2*kk+1)*HH + y)*WW + xx];
            float py = (float)(y  + i - 1) + oy;
            float px = (float)(xx + j - 1) + ox;
            float fy = floorf(py), fx = floorf(px);
            int yq = (int)fy, xq = (int)fx;
            float wy = py - fy, wx = px - fx;
            float vy0 = ((unsigned)yq     < (unsigned)HH) ? 1.f : 0.f;
            float vy1 = ((unsigned)(yq+1) < (unsigned)HH) ? 1.f : 0.f;
            float vx0 = ((unsigned)xq     < (unsigned)WW) ? 1.f : 0.f;
            float vx1 = ((unsigned)(xq+1) < (unsigned)WW) ? 1.f : 0.f;
            float uA = (1.f - wy)*vy0, uB = wy*vy1;
            float wA = (1.f - wx)*vx0, wB = wx*vx1;
            int yb0 = min(max(yq,   0), HH-1);
            int yb1 = min(max(yq+1, 0), HH-1);
            int xc0 = min(max(xq,   0), WW-1);
            int xc1 = min(max(xq+1, 0), WW-1);
            float* mp = M_s[mb] + tid*8;
            mp[0] = __uint_as_float((uint32_t)((yb0*WW + xc0)*CC));
            mp[1] = __uint_as_float((uint32_t)((yb1*WW + xc0)*CC));
            mp[2] = __uint_as_float((uint32_t)((xc1 - xc0)*CC));
            mp[3] = uA; mp[4] = uB; mp[5] = wA; mp[6] = wB; mp[7] = 0.f;
        }
    };
    auto stage_B = [&](int kk, int bf) {
        const uint4* src = (const uint4*)(g_dwTh + kk*4096);
        #pragma unroll 2
        for (int t = tid; t < 512; t += 256) {
            int o = t >> 3, w4 = t & 7;
            uint32_t dst = smaddr(&B_s[bf][o*36 + w4*4]);
            asm volatile("cp.async.ca.shared.global [%0], [%1], 16;"
                         :: "r"(dst), "l"(&src[o*8 + w4]) : "memory");
        }
        asm volatile("cp.async.commit_group;" ::: "memory");
    };
    auto gather = [&](int abuf, int mb) {
        const int c8 = lid & 7, pq = lid >> 3;
        #pragma unroll
        for (int it = 0; it < 2; ++it) {
            int px = (wid << 3) + (it << 2) + pq;
            const float* mp = M_s[mb] + px*8;
            float4 m0 = *(const float4*)mp;
            float4 m1 = *(const float4*)(mp + 4);
            uint32_t base0 = __float_as_uint(m0.x);
            uint32_t base1 = __float_as_uint(m0.y);
            uint32_t dx    = __float_as_uint(m0.z);
            __half2 uA2 = __float2half2_rn(m0.w);
            __half2 uB2 = __float2half2_rn(m1.x);
            __half2 wA2 = __float2half2_rn(m1.y);
            __half2 wB2 = __float2half2_rn(m1.z);
            uint4 cA0 = ((const uint4*)(xh + base0     ))[c8];
            uint4 cA1 = ((const uint4*)(xh + base0 + dx))[c8];
            uint4 cB0 = ((const uint4*)(xh + base1     ))[c8];
            uint4 cB1 = ((const uint4*)(xh + base1 + dx))[c8];
            const uint32_t* wa0 = (const uint32_t*)&cA0;
            const uint32_t* wa1 = (const uint32_t*)&cA1;
            const uint32_t* wb0 = (const uint32_t*)&cB0;
            const uint32_t* wb1 = (const uint32_t*)&cB1;
            uint4 out;
            uint32_t* ow = (uint32_t*)&out;
            #pragma unroll
            for (int p = 0; p < 4; ++p) {
                __half2 a0 = *(const __half2*)&wa0[p];
                __half2 a1 = *(const __half2*)&wa1[p];
                __half2 b0 = *(const __half2*)&wb0[p];
                __half2 b1 = *(const __half2*)&wb1[p];
                __half2 t0 = __hfma2(uA2, a0, __hmul2(uB2, b0));
                __half2 t1 = __hfma2(uA2, a1, __hmul2(uB2, b1));
                __half2 r  = __hfma2(wA2, t0, __hmul2(wB2, t1));
                ow[p] = *(const uint32_t*)&r;
            }
            ((uint4*)(&A_s[abuf][px*36]))[c8] = out;
        }
    };

    float d[2][2][4];
    #pragma unroll
    for (int mt = 0; mt < 2; ++mt)
        #pragma unroll
        for (int nt = 0; nt < 2; ++nt)
            { d[mt][nt][0]=0.f; d[mt][nt][1]=0.f; d[mt][nt][2]=0.f; d[mt][nt][3]=0.f; }

    const int mg = wid & 1, ng = wid >> 1;
    const int l8 = lid & 7, quad = lid >> 3;

    compute_meta(0, 0);
    __syncthreads();
    stage_B(0, 0);
    gather(0, 0);
    compute_meta(1, 1);
    asm volatile("cp.async.wait_group 0;" ::: "memory");
    __syncthreads();

    #pragma unroll 1
    for (int kk = 0; kk < 9; ++kk) {
        const int buf = kk & 1, nxt = buf ^ 1;
        if (kk < 8) {
            stage_B(kk + 1, nxt);
            if (kk < 7) compute_meta(kk + 2, buf);
            gather(nxt, nxt);
        }
        {
            const uint32_t* Ab = A_s[buf];
            const uint32_t* Bb = B_s[buf];
            const int arow_add = (quad & 1) ? 8 : 0;
            const int acol_add = (quad & 2) ? 4 : 0;
            const int bcol_add = (lid & 8) ? 4 : 0;
            #pragma unroll
            for (int s = 0; s < 4; ++s) {
                uint32_t a[2][4];
                #pragma unroll
                for (int mt = 0; mt < 2; ++mt) {
                    const int row = (mg*2 + mt)*16 + l8 + arow_add;
                    uint32_t addr = smaddr(&Ab[row*36 + s*8 + acol_add]);
                    LDSM_X4(a[mt][0], a[mt][1], a[mt][2], a[mt][3], addr);
                }
                #pragma unroll
                for (int nt = 0; nt < 2; ++nt) {
                    const int brow = (ng*2 + nt)*8 + l8;
                    uint32_t baddr = smaddr(&Bb[brow*36 + s*8 + bcol_add]);
                    uint32_t b0, b1;
                    LDSM_X2(b0, b1, baddr);
                    MMA_F16(d[0][nt][0], d[0][nt][1], d[0][nt][2], d[0][nt][3],
                            a[0][0], a[0][1], a[0][2], a[0][3], b0, b1);
                    MMA_F16(d[1][nt][0], d[1][nt][1], d[1][nt][2], d[1][nt][3],
                            a[1][0], a[1][1], a[1][2], a[1][3], b0, b1);
                }
            }
        }
        if (kk < 8) asm volatile("cp.async.wait_group 0;" ::: "memory");
        __syncthreads();
    }

    const int r4 = lid >> 2, klo = lid & 3;
    #pragma unroll
    for (int nt = 0; nt < 2; ++nt) {
        const int o0 = (ng*2 + nt)*8 + klo*2;
        const int o1 = o0 + 1;
        const float sc0 = sc_s[o0], sh0 = sh_s[o0];
        const float sc1 = sc_s[o1], sh1 = sh_s[o1];
        float s0 = 0.f, s1 = 0.f;
        #pragma unroll
        for (int mt = 0; mt < 2; ++mt) {
            const int p0 = (mg*2 + mt)*16 + r4, p1 = p0 + 8;
            float v00 = d[mt][nt][0]*sc0 + sh0;
            float v01 = d[mt][nt][1]*sc1 + sh1;
            float v10 = d[mt][nt][2]*sc0 + sh0;
            float v11 = d[mt][nt][3]*sc1 + sh1;
            g_h[((size_t)(b*CC + o0)*HH + y)*WW + x0b + p0] = v00;
            g_h[((size_t)(b*CC + o1)*HH + y)*WW + x0b + p0] = v01;
            g_h[((size_t)(b*CC + o0)*HH + y)*WW + x0b + p1] = v10;
            g_h[((size_t)(b*CC + o1)*HH + y)*WW + x0b + p1] = v11;
            s0 += v00 + v10;
            s1 += v01 + v11;
        }
        #pragma unroll
        for (int off = 4; off < 32; off <<= 1) {
            s0 += __shfl_xor_sync(0xffffffffu, s0, off);
            s1 += __shfl_xor_sync(0xffffffffu, s1, off);
        }
        if (r4 == 0) {
            atomicAdd(&g_pool[b*CC + o0], s0);
            atomicAdd(&g_pool[b*CC + o1], s1);
        }
    }
}

// ---------------------------------------------------------------------------
// K3: SE MLP (hid=4)
// ---------------------------------------------------------------------------
__global__ __launch_bounds__(256) void ca_kernel(
        const float* __restrict__ w1, const float* __restrict__ b1,
        const float* __restrict__ w2, const float* __restrict__ b2) {
    __shared__ float t[BB*HID];
    const int tid = threadIdx.x;
    const int b = tid >> 6, c = tid & 63;
    if (c < HID) {
        float s = b1[c];
        for (int cc = 0; cc < CC; ++cc)
            s += w1[c*CC + cc] * (g_pool[b*CC + cc] * (1.f/(float)HWX));
        t[b*HID + c] = fmaxf(s, 0.f);
    }
    __syncthreads();
    float s = b2[c];
    #pragma unroll
    for (int h = 0; h < HID; ++h) s += w2[c*HID + h] * t[b*HID + h];
    g_cw[tid] = 1.f / (1.f + expf(-s));
}

// ---------------------------------------------------------------------------
// K4: Y GEMM: Y[p, tap] = sum_c (sa_w[c,tap]*cw[c]) * h[c,p]  (R13, validated)
// ---------------------------------------------------------------------------
__global__ __launch_bounds__(256) void y_gemm_kernel(
        const float* __restrict__ sa_w) {
    __shared__ uint32_t A_s[64*36];
    __shared__ uint32_t B_s[56*36];
    __shared__ float ts[64*33];

    const int tid = threadIdx.x;
    const int wid = tid >> 5, lid = tid & 31;
    const int b   = blockIdx.y;
    const int p0b = blockIdx.x * 64;

    for (int e = tid; e < 56*32; e += 256) {
        int tap = e >> 5, c2 = e & 31;
        __half2 v = __half2half2(__float2half(0.f));
        if (tap < 49) {
            float w0 = sa_w[(2*c2  )*49 + tap] * g_cw[b*CC + 2*c2];
            float w1 = sa_w[(2*c2+1)*49 + tap] * g_cw[b*CC + 2*c2 + 1];
            v = __floats2half2_rn(w0, w1);
        }
        B_s[tap*36 + c2] = *(const uint32_t*)&v;
    }

    const int px5 = tid & 31, cg = tid >> 5;
    #pragma unroll
    for (int sub = 0; sub < 2; ++sub) {
        __syncthreads();
        #pragma unroll
        for (int it = 0; it < 8; ++it) {
            int ch = it*8 + cg;
            ts[ch*33 + px5] = g_h[((size_t)(b*CC + ch))*HWX + p0b + sub*32 + px5];
        }
        __syncthreads();
        const int c2 = tid & 31;
        #pragma unroll
        for (int it = 0; it < 4; ++it) {
            int pl = it*8 + (tid >> 5);
            __half2 h = __floats2half2_rn(ts[(2*c2)*33 + pl], ts[(2*c2+1)*33 + pl]);
            A_s[(sub*32 + pl)*36 + c2] = *(const uint32_t*)&h;
        }
    }
    __syncthreads();

    const int mt = wid & 3, ng = wid >> 2;
    const int r4 = lid >> 2, klo = lid & 3;
    const int nt0 = ng*4, ntn = ng ? 3 : 4;

    float d0[4], d1[4], d2[4], d3[4];
    #pragma unroll
    for (int i = 0; i < 4; ++i) { d0[i]=0.f; d1[i]=0.f; d2[i]=0.f; d3[i]=0.f; }

    #pragma unroll
    for (int s = 0; s < 4; ++s) {
        const int kw = s*8 + klo;
        const int row = mt*16 + r4;
        uint32_t a0 = A_s[ row     *36 + kw    ];
        uint32_t a1 = A_s[(row + 8)*36 + kw    ];
        uint32_t a2 = A_s[ row     *36 + kw + 4];
        uint32_t a3 = A_s[(row + 8)*36 + kw + 4];
        #pragma unroll
        for (int ni = 0; ni < 4; ++ni) {
            if (ni < ntn) {
                const int orow = (nt0 + ni)*8 + r4;
                uint32_t b0 = B_s[orow*36 + kw];
                uint32_t b1 = B_s[orow*36 + kw + 4];
                MMA_F16(d0[ni], d1[ni], d2[ni], d3[ni], a0, a1, a2, a3, b0, b1);
            }
        }
    }

    const int pA = p0b + mt*16 + r4;
    const int pB = pA + 8;
    #pragma unroll
    for (int ni = 0; ni < 4; ++ni) {
        if (ni < ntn) {
            int t0 = (nt0 + ni)*8 + klo*2;
            int t1 = t0 + 1;
            if (t0 < 49) {
                g_Yh[((size_t)(b*49 + t0))*HWX + pA] = __float2half(d0[ni]);
                g_Yh[((size_t)(b*49 + t0))*HWX + pB] = __float2half(d2[ni]);
            }
            if (t1 < 49) {
                g_Yh[((size_t)(b*49 + t1))*HWX + pA] = __float2half(d1[ni]);
                g_Yh[((size_t)(b*49 + t1))*HWX + pB] = __float2half(d3[ni]);
            }
        }
    }
}

// ---------------------------------------------------------------------------
// K5: final: sw = sigmoid(sum_tap Y[p+Delta,tap] + b); out = h*cw*sw
// ---------------------------------------------------------------------------
__global__ __launch_bounds__(256) void final_kernel(
        const float* __restrict__ sa_b, float* __restrict__ out) {
    __shared__ float cws[CC];
    const int idx = blockIdx.x*256 + threadIdx.x;
    const int b = idx / HWX;
    const int p = idx % HWX;
    const int y = p / WW, x = p % WW;

    if (threadIdx.x < CC) cws[threadIdx.x] = g_cw[b*CC + threadIdx.x];
    __syncthreads();

    float acc = sa_b[0];
    const __half* Yb = g_Yh + (size_t)b*49*HWX;
    #pragma unroll
    for (int dy = 0; dy < 7; ++dy) {
        int yy = y + dy - 3;
        if ((unsigned)yy >= (unsigned)HH) continue;
        #pragma unroll
        for (int dx = 0; dx < 7; ++dx) {
            int xx = x + dx - 3;
            if ((unsigned)xx >= (unsigned)WW) continue;
            acc += __half2float(Yb[(size_t)(dy*7 + dx)*HWX + yy*WW + xx]);
        }
    }
    float sw = 1.f / (1.f + expf(-acc));

    const float* hb = g_h + (size_t)b*CC*HWX + p;
    float* ob = out + (size_t)b*CC*HWX + p;
    #pragma unroll 8
    for (int c = 0; c < CC; ++c)
        ob[(size_t)c*HWX] = hb[(size_t)c*HWX] * cws[c] * sw;
}

// ---------------------------------------------------------------------------
extern "C" void kernel_launch(void* const* d_in, const int* in_sizes, int n_in,
                              void* d_out, int out_size) {
    const float* x      = (const float*)d_in[0];
    const float* off_w  = (const float*)d_in[1];
    const float* off_b  = (const float*)d_in[2];
    const float* dw     = (const float*)d_in[3];
    const float* db     = (const float*)d_in[4];
    const float* bn_g   = (const float*)d_in[5];
    const float* bn_b   = (const float*)d_in[6];
    const float* bn_m   = (const float*)d_in[7];
    const float* bn_v   = (const float*)d_in[8];
    const float* ca_w1  = (const float*)d_in[9];
    const float* ca_b1  = (const float*)d_in[10];
    const float* ca_w2  = (const float*)d_in[11];
    const float* ca_b2  = (const float*)d_in[12];
    const float* sa_w   = (const float*)d_in[13];
    const float* sa_b   = (const float*)d_in[14];
    float* out = (float*)d_out;

    cudaFuncSetAttribute(offset_conv_kernel,
                         cudaFuncAttributeMaxDynamicSharedMemorySize,
                         OC_SMEM_BYTES);

    const int prep_blocks = NHWC_BLOCKS + (9*CC*CC + 9*24*36 + 255)/256;
    prep_kernel       <<<prep_blocks, 256>>>(x, dw, off_w);
    offset_conv_kernel<<<dim3(WW/64, HH/4, BB), 256, OC_SMEM_BYTES>>>(off_b);
    deform_bn_kernel  <<<dim3(WW/64, HH, BB), 256>>>(db, bn_g, bn_b, bn_m, bn_v);
    ca_kernel         <<<1, 256>>>(ca_w1, ca_b1, ca_w2, ca_b2);
    y_gemm_kernel     <<<dim3(HWX/64, BB), 256>>>(sa_w);
    final_kernel      <<<BB*HWX/256, 256>>>(sa_b, out);
}